// round 15
// baseline (speedup 1.0000x reference)
#include <cuda_runtime.h>
#include <cuda_fp16.h>
#include <math.h>
#include <stdint.h>

// ---------------- problem constants ----------------
constexpr int BB     = 2;
constexpr int LL     = 2048;
constexpr int HID    = 2560;
constexpr int NH     = 16;
constexpr int NKV    = 4;
constexpr int HD     = 256;
constexpr int GQA    = NH / NKV;      // 4
constexpr int INNER  = NH * HD;       // 4096
constexpr int ROWS   = BB * LL;       // 4096
constexpr int NQKV   = 2 * INNER + 2 * NKV * HD;   // 10240
constexpr float EPS  = 1e-6f;

// ---------------- scratch (device globals) ----------------------------------
__device__ float  g_qkv [(size_t)ROWS * NQKV];       // fused q|gate|k|v
__device__ __half g_q16 [(size_t)BB * NH  * LL * HD];
__device__ __half g_k16 [(size_t)BB * NKV * LL * HD];
__device__ __half g_v16 [(size_t)BB * NKV * LL * HD];
// fragment-packed fp16 GEMM operands
__device__ __half g_xp   [(size_t)ROWS * HID];
__device__ __half g_attp [(size_t)ROWS * INNER];     // written by attn epilogue
__device__ __half g_wqkvp[(size_t)HID * NQKV];
__device__ __half g_wop  [(size_t)INNER * HID];

// ================= mma / ldmatrix helpers ====================================
__device__ __forceinline__ void mma16(float* d, uint32_t a0, uint32_t a1,
                                      uint32_t a2, uint32_t a3,
                                      uint32_t b0, uint32_t b1) {
    asm volatile(
        "mma.sync.aligned.m16n8k16.row.col.f32.f16.f16.f32 "
        "{%0,%1,%2,%3}, {%4,%5,%6,%7}, {%8,%9}, {%0,%1,%2,%3};"
        : "+f"(d[0]), "+f"(d[1]), "+f"(d[2]), "+f"(d[3])
        : "r"(a0), "r"(a1), "r"(a2), "r"(a3), "r"(b0), "r"(b1));
}

__device__ __forceinline__ void ldsm_x2_t(uint32_t& r0, uint32_t& r1, uint32_t addr) {
    asm volatile("ldmatrix.sync.aligned.m8n8.x2.trans.shared.b16 {%0,%1}, [%2];"
                 : "=r"(r0), "=r"(r1) : "r"(addr));
}

__device__ __forceinline__ void ldsm_x4(uint32_t& r0, uint32_t& r1,
                                        uint32_t& r2, uint32_t& r3, uint32_t addr) {
    asm volatile("ldmatrix.sync.aligned.m8n8.x4.shared.b16 {%0,%1,%2,%3}, [%4];"
                 : "=r"(r0), "=r"(r1), "=r"(r2), "=r"(r3) : "r"(addr));
}

__device__ __forceinline__ float ex2f(float x) {
    float r; asm("ex2.approx.f32 %0, %1;" : "=f"(r) : "f"(x));
    return r;
}

// ================= operand packing (fp16 fragment layout) ====================
__global__ void __launch_bounds__(256) pack_a(
    const float* __restrict__ A, __half* __restrict__ Ap, int K)
{
    size_t slot = (size_t)blockIdx.x * 256 + threadIdx.x;
    int lane = slot & 31, mb = (slot >> 5) & 7, ks = (slot >> 8) & 1;
    size_t rest = slot >> 9;
    int KT = K / 32;
    int kt = (int)(rest % KT), mt = (int)(rest / KT);
    int g = lane >> 2, t = lane & 3;
    int row = mt * 128 + mb * 16 + g;
    int col = kt * 32 + ks * 16 + 2 * t;
    const float* r0 = &A[(size_t)row * K + col];
    const float* r1 = &A[(size_t)(row + 8) * K + col];
    __half h[8];
    h[0] = __float2half_rn(r0[0]); h[1] = __float2half_rn(r0[1]);
    h[2] = __float2half_rn(r1[0]); h[3] = __float2half_rn(r1[1]);
    h[4] = __float2half_rn(r0[8]); h[5] = __float2half_rn(r0[9]);
    h[6] = __float2half_rn(r1[8]); h[7] = __float2half_rn(r1[9]);
    *(uint4*)&Ap[slot * 8] = *(uint4*)h;
}

__global__ void __launch_bounds__(256) pack_b(
    const float* __restrict__ Bm, __half* __restrict__ Bp, int K, int N)
{
    size_t slot = (size_t)blockIdx.x * 256 + threadIdx.x;
    int lane = slot & 31, q = (slot >> 5) & 7, ks = (slot >> 8) & 1;
    size_t rest = slot >> 9;
    int KT = K / 32;
    int kt = (int)(rest % KT), nt = (int)(rest / KT);
    int g = lane >> 2, t = lane & 3;
    int k  = kt * 32 + ks * 16 + 2 * t;
    int n0 = nt * 128 + q * 16 + g;
    int n1 = n0 + 8;
    __half h[8];
    h[0] = __float2half_rn(Bm[(size_t)k * N + n0]);
    h[1] = __float2half_rn(Bm[(size_t)(k + 1) * N + n0]);
    h[2] = __float2half_rn(Bm[(size_t)(k + 8) * N + n0]);
    h[3] = __float2half_rn(Bm[(size_t)(k + 9) * N + n0]);
    h[4] = __float2half_rn(Bm[(size_t)k * N + n1]);
    h[5] = __float2half_rn(Bm[(size_t)(k + 1) * N + n1]);
    h[6] = __float2half_rn(Bm[(size_t)(k + 8) * N + n1]);
    h[7] = __float2half_rn(Bm[(size_t)(k + 9) * N + n1]);
    *(uint4*)&Bp[slot * 8] = *(uint4*)h;
}

// ============ fp16 mma GEMM: CTA 256x128, 8 warps (4m x 2n), 64x64 ==========
constexpr int NSTG   = 4;
constexpr int ASTG_B = 16384;                         // 2 mt-tiles per stage
constexpr int BSTG_B = 8192;
constexpr int GEMM_SMEM = NSTG * (ASTG_B + BSTG_B);   // 98304

__device__ __forceinline__ void cp16(uint32_t dst, const void* src) {
    asm volatile("cp.async.cg.shared.global [%0], [%1], 16;" :: "r"(dst), "l"(src));
}

__global__ void __launch_bounds__(256) gemm_tc(
    const __half* __restrict__ Ap, const __half* __restrict__ Bp,
    float* __restrict__ C, int K, int ldc)
{
    extern __shared__ char smem[];
    char* Abuf = smem;
    char* Bbuf = smem + NSTG * ASTG_B;
    const uint32_t sA = (uint32_t)__cvta_generic_to_shared(Abuf);
    const uint32_t sB = (uint32_t)__cvta_generic_to_shared(Bbuf);

    const int tid  = threadIdx.x;
    const int wid  = tid >> 5;
    const int lane = tid & 31;
    const int wm   = wid & 3;                 // m offset wm*64
    const int wn   = wid >> 2;                // n offset wn*64
    const int wmt  = wm >> 1;                 // which mt tile (0/1) in stage
    const int mb0  = (wm & 1) * 4;            // first 16-row block in mt tile
    const int g    = lane >> 2;
    const int t    = lane & 3;
    const int KT   = K / 32;

    // A: mt-major, kt-minor: offset(mt,kt) = (mt*KT + kt) * 4096 halves.
    const __half* A0 = Ap + (size_t)(2 * blockIdx.y)     * KT * 4096;
    const __half* A1 = Ap + (size_t)(2 * blockIdx.y + 1) * KT * 4096;
    const size_t bbase = (size_t)blockIdx.x * KT * 4096;

    float d[4][8][4];
    #pragma unroll
    for (int i = 0; i < 4; i++)
        #pragma unroll
        for (int j = 0; j < 8; j++)
            #pragma unroll
            for (int r = 0; r < 4; r++) d[i][j][r] = 0.f;

    auto stage = [&](int buf, int s) {
        #pragma unroll
        for (int i = 0; i < 4; i++) {         // A: 1024 16B chunks
            int idx = tid + i * 256;
            const __half* src = (idx < 512)
                ? A0 + (size_t)s * 4096 + idx * 8
                : A1 + (size_t)s * 4096 + (idx - 512) * 8;
            cp16(sA + (uint32_t)(buf * ASTG_B + idx * 16), src);
        }
        #pragma unroll
        for (int i = 0; i < 2; i++) {         // B: 512 16B chunks
            int idx = tid + i * 256;
            cp16(sB + (uint32_t)(buf * BSTG_B + idx * 16),
                 Bp + bbase + (size_t)s * 4096 + idx * 8);
        }
        asm volatile("cp.async.commit_group;" ::: "memory");
    };

    stage(0, 0);
    stage(1, 1);
    stage(2, 2);

    for (int s = 0; s < KT; s++) {
        asm volatile("cp.async.wait_group 2;" ::: "memory");
        __syncthreads();
        if (s + 3 < KT) stage((s + 3) & (NSTG - 1), s + 3);
        else asm volatile("cp.async.commit_group;" ::: "memory");

        const uint4* At = (const uint4*)(Abuf + (s & (NSTG - 1)) * ASTG_B)
                          + wmt * 512;
        const uint4* Bt = (const uint4*)(Bbuf + (s & (NSTG - 1)) * BSTG_B);
        #pragma unroll
        for (int ks = 0; ks < 2; ks++) {
            uint4 a[4], bb[4];
            #pragma unroll
            for (int i = 0; i < 4; i++)
                a[i] = At[(ks * 8 + mb0 + i) * 32 + lane];
            #pragma unroll
            for (int p = 0; p < 4; p++)
                bb[p] = Bt[(ks * 8 + wn * 4 + p) * 32 + lane];
            #pragma unroll
            for (int i = 0; i < 4; i++)
                #pragma unroll
                for (int p = 0; p < 4; p++) {
                    mma16(d[i][2 * p],     a[i].x, a[i].y, a[i].z, a[i].w, bb[p].x, bb[p].y);
                    mma16(d[i][2 * p + 1], a[i].x, a[i].y, a[i].z, a[i].w, bb[p].z, bb[p].w);
                }
        }
    }

    #pragma unroll
    for (int i = 0; i < 4; i++) {
        int r = blockIdx.y * 256 + wm * 64 + i * 16 + g;
        #pragma unroll
        for (int j = 0; j < 8; j++) {
            int c = blockIdx.x * 128 + wn * 64 + j * 8 + 2 * t;
            *(float2*)&C[(size_t)r * ldc + c]       = make_float2(d[i][j][0], d[i][j][1]);
            *(float2*)&C[(size_t)(r + 8) * ldc + c] = make_float2(d[i][j][2], d[i][j][3]);
        }
    }
}

// ---------------- fused warp-level RMSNorm + RoPE (Q,K) + V copy ------------
__device__ __forceinline__ float warp_sumsq(const float* x)
{
    float ss = 0.f;
    #pragma unroll
    for (int j = 0; j < 8; j++) ss = fmaf(x[j], x[j], ss);
    #pragma unroll
    for (int o = 16; o; o >>= 1) ss += __shfl_xor_sync(0xffffffffu, ss, o);
    return ss;
}

__global__ void __launch_bounds__(768) qkv_prep(
    const float* __restrict__ qkv, const float* __restrict__ cosb,
    const float* __restrict__ sinb, const float* __restrict__ qw,
    const float* __restrict__ kw)
{
    int row  = blockIdx.x;
    int wid  = threadIdx.x >> 5;
    int lane = threadIdx.x & 31;
    int l    = row & (LL - 1), b = row >> 11;

    if (wid < 16) {                           // Q heads
        int h = wid;
        const float* src = qkv + (size_t)row * NQKV + h * HD;
        float x[8];
        #pragma unroll
        for (int j = 0; j < 8; j++) x[j] = src[lane + 32 * j];
        float rms = rsqrtf(warp_sumsq(x) * (1.0f / HD) + EPS);
        float xn[8];
        #pragma unroll
        for (int j = 0; j < 8; j++) xn[j] = x[j] * rms * qw[lane + 32 * j];
        __half* dst = g_q16 + (((size_t)b * NH + h) * LL + l) * HD;
        #pragma unroll
        for (int j = 0; j < 8; j++) {
            int   d   = lane + 32 * j;
            float rot = (j < 4) ? -xn[j + 4] : xn[j - 4];
            float c   = cosb[(size_t)l * HD + d];
            float s   = sinb[(size_t)l * HD + d];
            dst[d] = __float2half_rn(xn[j] * c + rot * s);
        }
    } else if (wid < 20) {                    // K heads
        int h = wid - 16;
        const float* src = qkv + (size_t)row * NQKV + 2 * INNER + h * HD;
        float x[8];
        #pragma unroll
        for (int j = 0; j < 8; j++) x[j] = src[lane + 32 * j];
        float rms = rsqrtf(warp_sumsq(x) * (1.0f / HD) + EPS);
        float xn[8];
        #pragma unroll
        for (int j = 0; j < 8; j++) xn[j] = x[j] * rms * kw[lane + 32 * j];
        __half* dst = g_k16 + (((size_t)b * NKV + h) * LL + l) * HD;
        #pragma unroll
        for (int j = 0; j < 8; j++) {
            int   d   = lane + 32 * j;
            float rot = (j < 4) ? -xn[j + 4] : xn[j - 4];
            float c   = cosb[(size_t)l * HD + d];
            float s   = sinb[(size_t)l * HD + d];
            dst[d] = __float2half_rn(xn[j] * c + rot * s);
        }
    } else {                                  // V heads: fp32 -> fp16 copy
        int h = wid - 20;
        const float* src = qkv + (size_t)row * NQKV + 2 * INNER + NKV * HD + h * HD;
        __half* dst = g_v16 + (((size_t)b * NKV + h) * LL + l) * HD;
        #pragma unroll
        for (int j = 0; j < 8; j++) {
            int d = lane + 32 * j;
            dst[d] = __float2half_rn(src[d]);
        }
    }
}

// ---------------- mma flash attention + fused gate + packed-A epilogue ------
constexpr int QTILE = 64;
constexpr int KTILE = 32;
constexpr int QS_LD = 264;
constexpr int KS_LD = 264;
constexpr int ATT_SMEM = (QTILE * QS_LD + 2 * KTILE * KS_LD) * 2;  // 67584

__global__ void __launch_bounds__(128) attn_mma()
{
    extern __shared__ __half sm[];
    __half* Qs = sm;                        // [64][264]
    __half* Ks = Qs + QTILE * QS_LD;        // [32][264]
    __half* Vs = Ks + KTILE * KS_LD;        // [32][264] row-major (ldmatrix.trans)

    const int b  = blockIdx.z, h = blockIdx.y;
    const int q0 = (gridDim.x - 1 - blockIdx.x) * QTILE;   // heavy CTAs first
    const int kv = h >> 2;
    const int tid = threadIdx.x, wid = tid >> 5, lane = tid & 31;
    const int g = lane >> 2, t = lane & 3;
    const int wr = wid * 16;

    const __half* Qg = g_q16 + (((size_t)b * NH  + h)  * LL + q0) * HD;
    const __half* Kg = g_k16 + (((size_t)b * NKV + kv) * LL) * HD;
    const __half* Vg = g_v16 + (((size_t)b * NKV + kv) * LL) * HD;

    // stage Q once
    #pragma unroll
    for (int i = 0; i < 16; i++) {
        int idx = tid + i * 128;
        int r = idx >> 5, c = (idx & 31) * 8;
        *(uint4*)&Qs[r * QS_LD + c] = *(const uint4*)&Qg[(size_t)r * HD + c];
    }

    const int lrow = ((lane >> 3) & 1) * 8 + (lane & 7);
    const int lcol = (lane >> 4) * 8;
    const uint32_t sQfrag  = (uint32_t)__cvta_generic_to_shared(Qs)
                             + (uint32_t)(wr + lrow) * (QS_LD * 2) + lcol * 2;
    const uint32_t sKfrag  = (uint32_t)__cvta_generic_to_shared(Ks)
                             + (uint32_t)lrow * (KS_LD * 2) + lcol * 2;
    const uint32_t sKfrag2 = sKfrag + 16 * KS_LD * 2;
    const uint32_t sVrow   = (uint32_t)__cvta_generic_to_shared(Vs)
                             + (uint32_t)(lane & 15) * KS_LD * 2;
    const uint32_t sVrow2  = sVrow + 16 * KS_LD * 2;

    float m2[2]    = {-1e30f, -1e30f};
    float lrowv[2] = {0.f, 0.f};
    float O[32][4];
    #pragma unroll
    for (int n = 0; n < 32; n++) { O[n][0] = O[n][1] = O[n][2] = O[n][3] = 0.f; }

    const float cscale = 0.09016994f;       // (1/16) * log2(e)
    const int ntiles = q0 / KTILE + 2;

    for (int tile = 0; tile < ntiles; tile++) {
        const int kb = tile * KTILE;
        __syncthreads();
        #pragma unroll
        for (int i = 0; i < 8; i++) {
            int idx = tid + i * 128;
            int r = idx >> 5, c = (idx & 31) * 8;
            *(uint4*)&Ks[r * KS_LD + c] = *(const uint4*)&Kg[(size_t)(kb + r) * HD + c];
            *(uint4*)&Vs[r * KS_LD + c] = *(const uint4*)&Vg[(size_t)(kb + r) * HD + c];
        }
        __syncthreads();

        if (kb > q0 + wr + 15) continue;

        float s[4][4];
        #pragma unroll
        for (int nt = 0; nt < 4; nt++)
            #pragma unroll
            for (int r = 0; r < 4; r++) s[nt][r] = 0.f;
        #pragma unroll
        for (int c = 0; c < 16; c++) {
            uint32_t a0, a1, a2, a3, k0, k1, k2, k3, k4, k5, k6, k7;
            ldsm_x4(a0, a1, a2, a3, sQfrag  + c * 32);
            ldsm_x4(k0, k1, k2, k3, sKfrag  + c * 32);
            ldsm_x4(k4, k5, k6, k7, sKfrag2 + c * 32);
            mma16(s[0], a0, a1, a2, a3, k0, k2);
            mma16(s[1], a0, a1, a2, a3, k1, k3);
            mma16(s[2], a0, a1, a2, a3, k4, k6);
            mma16(s[3], a0, a1, a2, a3, k5, k7);
        }

        if (kb + 31 > q0 + wr) {
            int r0 = q0 + wr + g, r8 = r0 + 8;
            #pragma unroll
            for (int nt = 0; nt < 4; nt++) {
                int kp = kb + nt * 8 + 2 * t;
                if (kp     > r0) s[nt][0] = -1e30f;
                if (kp + 1 > r0) s[nt][1] = -1e30f;
                if (kp     > r8) s[nt][2] = -1e30f;
                if (kp + 1 > r8) s[nt][3] = -1e30f;
            }
        }

        float r0m = fmaxf(fmaxf(s[0][0], s[0][1]), fmaxf(s[1][0], s[1][1]));
        r0m = fmaxf(r0m, fmaxf(fmaxf(s[2][0], s[2][1]), fmaxf(s[3][0], s[3][1])));
        float r8m = fmaxf(fmaxf(s[0][2], s[0][3]), fmaxf(s[1][2], s[1][3]));
        r8m = fmaxf(r8m, fmaxf(fmaxf(s[2][2], s[2][3]), fmaxf(s[3][2], s[3][3])));
        r0m = fmaxf(r0m, __shfl_xor_sync(0xffffffffu, r0m, 1));
        r0m = fmaxf(r0m, __shfl_xor_sync(0xffffffffu, r0m, 2));
        r8m = fmaxf(r8m, __shfl_xor_sync(0xffffffffu, r8m, 1));
        r8m = fmaxf(r8m, __shfl_xor_sync(0xffffffffu, r8m, 2));
        float m2n0 = fmaxf(m2[0], r0m * cscale);
        float m2n8 = fmaxf(m2[1], r8m * cscale);
        float corr0 = ex2f(m2[0] - m2n0);
        float corr8 = ex2f(m2[1] - m2n8);
        m2[0] = m2n0; m2[1] = m2n8;

        float p[4][4];
        #pragma unroll
        for (int nt = 0; nt < 4; nt++) {
            p[nt][0] = ex2f(fmaf(s[nt][0], cscale, -m2n0));
            p[nt][1] = ex2f(fmaf(s[nt][1], cscale, -m2n0));
            p[nt][2] = ex2f(fmaf(s[nt][2], cscale, -m2n8));
            p[nt][3] = ex2f(fmaf(s[nt][3], cscale, -m2n8));
        }
        lrowv[0] = lrowv[0] * corr0 + (p[0][0] + p[0][1]) + (p[1][0] + p[1][1])
                                    + (p[2][0] + p[2][1]) + (p[3][0] + p[3][1]);
        lrowv[1] = lrowv[1] * corr8 + (p[0][2] + p[0][3]) + (p[1][2] + p[1][3])
                                    + (p[2][2] + p[2][3]) + (p[3][2] + p[3][3]);

        uint32_t pc[2][4];
        #pragma unroll
        for (int ch = 0; ch < 2; ch++) {
            __half2 h0 = __float22half2_rn(make_float2(p[2*ch][0],   p[2*ch][1]));
            __half2 h1 = __float22half2_rn(make_float2(p[2*ch][2],   p[2*ch][3]));
            __half2 h2 = __float22half2_rn(make_float2(p[2*ch+1][0], p[2*ch+1][1]));
            __half2 h3 = __float22half2_rn(make_float2(p[2*ch+1][2], p[2*ch+1][3]));
            pc[ch][0] = *(uint32_t*)&h0;
            pc[ch][1] = *(uint32_t*)&h1;
            pc[ch][2] = *(uint32_t*)&h2;
            pc[ch][3] = *(uint32_t*)&h3;
        }

        #pragma unroll
        for (int n = 0; n < 32; n++) {
            O[n][0] *= corr0; O[n][1] *= corr0;
            O[n][2] *= corr8; O[n][3] *= corr8;
            uint32_t b0, b1;
            ldsm_x2_t(b0, b1, sVrow + n * 16);
            mma16(O[n], pc[0][0], pc[0][1], pc[0][2], pc[0][3], b0, b1);
            ldsm_x2_t(b0, b1, sVrow2 + n * 16);
            mma16(O[n], pc[1][0], pc[1][1], pc[1][2], pc[1][3], b0, b1);
        }
    }

    // ---- fused epilogue: 1/l, silu(gate), pack fp16 A-fragments ----
    float l0 = lrowv[0];
    l0 += __shfl_xor_sync(0xffffffffu, l0, 1);
    l0 += __shfl_xor_sync(0xffffffffu, l0, 2);
    float l8 = lrowv[1];
    l8 += __shfl_xor_sync(0xffffffffu, l8, 1);
    l8 += __shfl_xor_sync(0xffffffffu, l8, 2);
    float inv0 = __fdividef(1.f, l0);
    float inv8 = __fdividef(1.f, l8);

    const int r0l = q0 + wr + g;
    const int mt  = (b * LL + q0 + wr) >> 7;
    const int mb  = ((q0 & 64) >> 4) + wid;
    const float* gate0 = g_qkv + (size_t)(b * LL + r0l) * NQKV + INNER + h * HD;
    const float* gate8 = gate0 + (size_t)8 * NQKV;

    #pragma unroll
    for (int n = 0; n < 32; n += 2) {
        int kt = h * 8 + (n >> 2);
        int ks = (n >> 1) & 1;
        size_t off = (((size_t)mt * 128 + kt) * 512 + (ks * 8 + mb) * 32 + lane) * 8;
        int c0 = n * 8 + 2 * t;
        float2 gA0 = *(const float2*)&gate0[c0];
        float2 gB0 = *(const float2*)&gate8[c0];
        float2 gA1 = *(const float2*)&gate0[c0 + 8];
        float2 gB1 = *(const float2*)&gate8[c0 + 8];
        float sA0x = gA0.x / (1.f + __expf(-gA0.x));
        float sA0y = gA0.y / (1.f + __expf(-gA0.y));
        float sB0x = gB0.x / (1.f + __expf(-gB0.x));
        float sB0y = gB0.y / (1.f + __expf(-gB0.y));
        float sA1x = gA1.x / (1.f + __expf(-gA1.x));
        float sA1y = gA1.y / (1.f + __expf(-gA1.y));
        float sB1x = gB1.x / (1.f + __expf(-gB1.x));
        float sB1y = gB1.y / (1.f + __expf(-gB1.y));
        __half hb[8];
        hb[0] = __float2half_rn(O[n][0]     * inv0 * sA0x);
        hb[1] = __float2half_rn(O[n][1]     * inv0 * sA0y);
        hb[2] = __float2half_rn(O[n][2]     * inv8 * sB0x);
        hb[3] = __float2half_rn(O[n][3]     * inv8 * sB0y);
        hb[4] = __float2half_rn(O[n + 1][0] * inv0 * sA1x);
        hb[5] = __float2half_rn(O[n + 1][1] * inv0 * sA1y);
        hb[6] = __float2half_rn(O[n + 1][2] * inv8 * sB1x);
        hb[7] = __float2half_rn(O[n + 1][3] * inv8 * sB1y);
        *(uint4*)&g_attp[off] = *(uint4*)hb;
    }
}

// ---------------- launch ----------------------------------------------------
extern "C" void kernel_launch(void* const* d_in, const int* in_sizes, int n_in,
                              void* d_out, int out_size)
{
    const float* X    = (const float*)d_in[0];
    const float* cosb = (const float*)d_in[1];
    const float* sinb = (const float*)d_in[2];
    const float* Wq   = (const float*)d_in[3];
    const float* Wk   = (const float*)d_in[4];
    const float* Wv   = (const float*)d_in[5];
    const float* Wo   = (const float*)d_in[6];
    const float* qw   = (const float*)d_in[7];
    const float* kw   = (const float*)d_in[8];
    float* out = (float*)d_out;

    float* qkv;
    __half *xp, *attp, *wqkvp, *wop;
    cudaGetSymbolAddress((void**)&qkv,   g_qkv);
    cudaGetSymbolAddress((void**)&xp,    g_xp);
    cudaGetSymbolAddress((void**)&attp,  g_attp);
    cudaGetSymbolAddress((void**)&wqkvp, g_wqkvp);
    cudaGetSymbolAddress((void**)&wop,   g_wop);

    static bool attr_set = false;
    if (!attr_set) {
        cudaFuncSetAttribute(gemm_tc, cudaFuncAttributeMaxDynamicSharedMemorySize,
                             GEMM_SMEM);
        cudaFuncSetAttribute(attn_mma, cudaFuncAttributeMaxDynamicSharedMemorySize,
                             ATT_SMEM);
        attr_set = true;
    }

    constexpr int KTH = HID / 32;
    __half* wq_dst = wqkvp;
    __half* wk_dst = wqkvp + (size_t)(2 * INNER / 128) * KTH * 4096;
    __half* wv_dst = wk_dst + (size_t)(NKV * HD / 128) * KTH * 4096;

    // 0) operand packing
    pack_a<<<(unsigned)((size_t)ROWS * HID      / 2048), 256>>>(X,  xp,  HID);
    pack_b<<<(unsigned)((size_t)HID * 2 * INNER / 2048), 256>>>(Wq, wq_dst, HID, 2 * INNER);
    pack_b<<<(unsigned)((size_t)HID * NKV * HD  / 2048), 256>>>(Wk, wk_dst, HID, NKV * HD);
    pack_b<<<(unsigned)((size_t)HID * NKV * HD  / 2048), 256>>>(Wv, wv_dst, HID, NKV * HD);
    pack_b<<<(unsigned)((size_t)INNER * HID     / 2048), 256>>>(Wo, wop, INNER, HID);

    // 1) fused QKV projection (CTA 256x128)
    gemm_tc<<<dim3(NQKV / 128, ROWS / 256), 256, GEMM_SMEM>>>(xp, wqkvp, qkv, HID, NQKV);

    // 2) fused warp-level RMSNorm + RoPE -> fp16 (Q, K) + V copy
    qkv_prep<<<ROWS, 768>>>(qkv, cosb, sinb, qw, kw);

    // 3) mma flash attention (+ gate + pack fused in epilogue)
    attn_mma<<<dim3(LL / QTILE, NH, BB), 128, ATT_SMEM>>>();

    // 4) output projection (CTA 256x128)
    gemm_tc<<<dim3(HID / 128, ROWS / 256), 256, GEMM_SMEM>>>(attp, wop, out, INNER, HID);
}